// round 11
// baseline (speedup 1.0000x reference)
#include <cuda_runtime.h>
#include <cuda_fp16.h>
#include <math.h>

#define NPL   80
#define NYI   384
#define OSN   768
#define PAD   192
#define PLSZ  (768*768)
#define HALF_OUT ((size_t)NPL*NYI*NYI)

__device__ __half2 g_bufA[(size_t)NPL*OSN*OSN];
__device__ __half2 g_bufB[(size_t)NPL*OSN*OSN];
__device__ float4  g_twidB[128];   // [k][j]: {w^{3(2j)k}, w^{3(2j+1)k}}, w = e^{-2pi i/768}
__device__ float4  g_twidC[256];   // [k]:    {w^{k}, w^{2k}}

__constant__ float2 c_w16[10] = {
    { 1.0f,            0.0f},
    { 0.9238795325f,  -0.3826834324f},
    { 0.7071067812f,  -0.7071067812f},
    { 0.3826834324f,  -0.9238795325f},
    { 0.0f,           -1.0f},
    {-0.3826834324f,  -0.9238795325f},
    {-0.7071067812f,  -0.7071067812f},
    {-0.9238795325f,  -0.3826834324f},
    {-1.0f,            0.0f},
    {-0.9238795325f,   0.3826834324f}
};

__device__ __forceinline__ float2 cmulf(float2 a, float2 b){
    return make_float2(a.x*b.x - a.y*b.y, a.x*b.y + a.y*b.x);
}
__device__ __forceinline__ float2 caddf(float2 a, float2 b){ return make_float2(a.x+b.x, a.y+b.y); }
__device__ __forceinline__ float2 csubf(float2 a, float2 b){ return make_float2(a.x-b.x, a.y-b.y); }

template<bool INV>
__device__ __forceinline__ float2 twmul(float2 a, float2 w){
    if (INV) w.y = -w.y;
    return cmulf(a, w);
}

__device__ __forceinline__ unsigned f2hu(float x, float y){
    __half2 h = __floats2half2_rn(x, y);
    return *reinterpret_cast<unsigned*>(&h);
}
__device__ __forceinline__ float2 h2f(unsigned u){
    __half2 h = *reinterpret_cast<__half2*>(&u);
    return __half22float2(h);
}
__device__ __forceinline__ unsigned f2hu2(float2 v){ return f2hu(v.x, v.y); }

__global__ void k_twid(){
    int t = blockIdx.x*blockDim.x + threadIdx.x;
    const double TPI = -2.0*3.14159265358979323846/768.0;
    if (t < 128){
        int k = t >> 3, j = t & 7;
        double a0 = TPI*(double)(3*(2*j  )*k);
        double a1 = TPI*(double)(3*(2*j+1)*k);
        g_twidB[t] = make_float4((float)cos(a0), (float)sin(a0),
                                 (float)cos(a1), (float)sin(a1));
    }
    if (t < 256){
        double a0 = TPI*(double)t;
        double a1 = TPI*(double)(2*t);
        g_twidC[t] = make_float4((float)cos(a0), (float)sin(a0),
                                 (float)cos(a1), (float)sin(a1));
    }
}

__global__ void k_noop(){}

template<bool INV>
__device__ __forceinline__ void dft4(float2 &a0, float2 &a1, float2 &a2, float2 &a3){
    float2 t0=caddf(a0,a2), t1=csubf(a0,a2), t2=caddf(a1,a3), t3=csubf(a1,a3);
    a0 = caddf(t0,t2);  a2 = csubf(t0,t2);
    if (!INV){ a1 = make_float2(t1.x + t3.y, t1.y - t3.x);
               a3 = make_float2(t1.x - t3.y, t1.y + t3.x); }
    else     { a1 = make_float2(t1.x - t3.y, t1.y + t3.x);
               a3 = make_float2(t1.x + t3.y, t1.y - t3.x); }
}
template<bool INV>
__device__ __forceinline__ void dft16_pass1(float2 a[16]){
    #pragma unroll
    for (int n2 = 0; n2 < 4; ++n2)
        dft4<INV>(a[n2], a[n2+4], a[n2+8], a[n2+12]);
}
// pass1 specialized for inputs only in a[4..11] (legs 0,3 are exact zeros)
template<bool INV>
__device__ __forceinline__ void dft16_pass1_pruned(float2 a[16]){
    #pragma unroll
    for (int n2 = 0; n2 < 4; ++n2){
        float2 X = a[n2+4], Y = a[n2+8];     // dft4(0, X, Y, 0)
        float2 o0 = caddf(Y, X);
        float2 o2 = csubf(Y, X);
        float2 o1, o3;
        if (!INV){
            o1 = make_float2(X.y - Y.x, -(X.x + Y.y));
            o3 = make_float2(-(X.y + Y.x), X.x - Y.y);
        } else {
            o1 = make_float2(-(Y.x + X.y), X.x - Y.y);
            o3 = make_float2(X.y - Y.x, -(X.x + Y.y));
        }
        a[n2]=o0; a[n2+4]=o1; a[n2+8]=o2; a[n2+12]=o3;
    }
}
template<bool INV>
__device__ __forceinline__ void dft16_pass2(const float2 a[16], int k1, float2 y[4]){
    y[0] = a[4*k1];
    y[1] = twmul<INV>(a[4*k1+1], c_w16[k1]);
    y[2] = twmul<INV>(a[4*k1+2], c_w16[2*k1]);
    y[3] = twmul<INV>(a[4*k1+3], c_w16[3*k1]);
    dft4<INV>(y[0], y[1], y[2], y[3]);
}
template<bool INV>
__device__ __forceinline__ void rad3t(float2 &a0, float2 &a1, float2 &a2, float4 wc){
    a1 = twmul<INV>(a1, make_float2(wc.x, wc.y));
    a2 = twmul<INV>(a2, make_float2(wc.z, wc.w));
    float2 t = caddf(a1, a2);
    float2 d = csubf(a1, a2);
    float2 b0 = caddf(a0, t);
    float2 u  = make_float2(a0.x - 0.5f*t.x, a0.y - 0.5f*t.y);
    const float S = INV ? 0.86602540378443864676f : -0.86602540378443864676f;
    a0 = b0;
    a1 = make_float2(u.x - S*d.y, u.y + S*d.x);
    a2 = make_float2(u.x + S*d.y, u.y - S*d.x);
}

// Stage A store + stage B (strength-reduced swizzled smem addressing).
template<int LGN, bool INV>
__device__ __forceinline__ void fft_stAB(float2 a[16], unsigned* s, int idx, int col){
    const int NB = 1 << LGN;
    const int KW = (LGN == 2) ? 7 : 15;
    const int KS = LGN;
    {
        const int baseA = idx*(16*NB) + col;
        const int keyA  = (idx & KW) << KS;
        #pragma unroll
        for (int k1 = 0; k1 < 4; ++k1){
            float2 y[4];
            dft16_pass2<INV>(a, k1, y);
            #pragma unroll
            for (int k2 = 0; k2 < 4; ++k2){
                const int off = (k1 + 4*k2)*NB;
                s[baseA + (off ^ keyA)] = f2hu2(y[k2]);
            }
        }
    }
    __syncthreads();
    {
        const int b0 = idx*NB + col;
        const int q  = idx >> 4;
        #pragma unroll
        for (int r = 0; r < 16; ++r){
            const int key = ((q + 3*r) & KW) << KS;
            a[r] = h2f(s[(b0 ^ key) + 48*NB*r]);
        }
        const int k = idx & 15;
        #pragma unroll
        for (int j = 0; j < 8; ++j){
            float4 w2 = g_twidB[k*8 + j];
            if (j > 0) a[2*j] = twmul<INV>(a[2*j], make_float2(w2.x, w2.y));
            a[2*j+1] = twmul<INV>(a[2*j+1], make_float2(w2.z, w2.w));
        }
        dft16_pass1<INV>(a);
    }
    __syncthreads();
    {
        const int k  = idx & 15, j = idx >> 4;
        const int t  = k*NB + col;
        const int Cj = j*(256*NB);
        #pragma unroll
        for (int k1 = 0; k1 < 4; ++k1){
            float2 y[4];
            dft16_pass2<INV>(a, k1, y);
            #pragma unroll
            for (int k2 = 0; k2 < 4; ++k2){
                const int off = k1 + 4*k2;
                s[Cj + off*(16*NB) + (t ^ ((off & KW) << KS))] = f2hu2(y[k2]);
            }
        }
    }
    __syncthreads();
}

template<int LGN>
__device__ __forceinline__ int stC_base(int kk, int col){
    const int KW = (LGN == 2) ? 7 : 15;
    return (kk*(1<<LGN) + col) ^ (((kk >> 4) & KW) << LGN);
}

// ---------------- K1: row forward (192 thr, all active) ----------------
__global__ void __launch_bounds__(192, 6) k_row_fwd(const float* __restrict__ re,
                                                    const float* __restrict__ im){
    extern __shared__ unsigned s[];              // 3072
    int p = blockIdx.y, iy0 = blockIdx.x*4, tid = threadIdx.x;
    int col = tid & 3, idx = tid >> 2;
    {
        int iy = iy0 + col;
        size_t rb = ((size_t)p*NYI + iy)*NYI;
        float2 a[16];
        #pragma unroll
        for (int q = 0; q < 8; ++q){
            int ix = idx + 48*q;
            float sg = ((iy + ix) & 1) ? -1.f : 1.f;
            a[q+4] = make_float2(sg*re[rb + ix], sg*im[rb + ix]);
        }
        dft16_pass1_pruned<false>(a);
        fft_stAB<2,false>(a, s, idx, col);
    }
    #pragma unroll 1
    for (int w = tid; w < 1024; w += 192){
        int kk = w >> 2, c = w & 3;
        int b3 = stC_base<2>(kk, c);
        float2 a0 = h2f(s[b3       ]);
        float2 a1 = h2f(s[b3 + 1024]);
        float2 a2 = h2f(s[b3 + 2048]);
        rad3t<false>(a0, a1, a2, g_twidC[kk]);
        size_t base = ((size_t)p*OSN + PAD + iy0 + c)*OSN;
        *reinterpret_cast<unsigned*>(&g_bufA[base + kk      ]) = f2hu2(a0);
        *reinterpret_cast<unsigned*>(&g_bufA[base + kk + 256]) = f2hu2(a1);
        *reinterpret_cast<unsigned*>(&g_bufA[base + kk + 512]) = f2hu2(a2);
    }
}

// ---------------- K2: column forward (384 thr, all active) ----------------
__global__ void __launch_bounds__(384, 3) k_col_fwd(){
    extern __shared__ unsigned s[];              // 6144
    int p = blockIdx.y, x0 = blockIdx.x*8, tid = threadIdx.x;
    int col = tid & 7, idx = tid >> 3;
    {
        float2 a[16];
        #pragma unroll
        for (int q = 0; q < 8; ++q){
            int y = idx + 48*q + PAD;
            a[q+4] = h2f(*reinterpret_cast<const unsigned*>(
                &g_bufA[((size_t)p*OSN + y)*OSN + x0 + col]));
        }
        dft16_pass1_pruned<false>(a);
        fft_stAB<3,false>(a, s, idx, col);
    }
    size_t pb = (size_t)p*OSN*OSN + x0;
    #pragma unroll 1
    for (int w = tid; w < 2048; w += 384){
        int kk = w >> 3, c = w & 7;
        int b3 = stC_base<3>(kk, c);
        float2 a0 = h2f(s[b3       ]);
        float2 a1 = h2f(s[b3 + 2048]);
        float2 a2 = h2f(s[b3 + 4096]);
        rad3t<false>(a0, a1, a2, g_twidC[kk]);
        *reinterpret_cast<unsigned*>(&g_bufB[pb + c + (size_t)(kk      )*OSN]) = f2hu2(a0);
        *reinterpret_cast<unsigned*>(&g_bufB[pb + c + (size_t)(kk + 256)*OSN]) = f2hu2(a1);
        *reinterpret_cast<unsigned*>(&g_bufB[pb + c + (size_t)(kk + 512)*OSN]) = f2hu2(a2);
    }
}

// ---------------- K3: pointwise 5x5 subspace mixing ----------------
__global__ void __launch_bounds__(256, 4) k_einsum(const float* __restrict__ kre,
                                                   const float* __restrict__ kim){
    int px = blockIdx.x*256 + threadIdx.x;
    if (px >= PLSZ) return;
    const float sc = 1.0f/589824.0f;
    float2 kv[25];
    #pragma unroll
    for (int q = 0; q < 25; ++q)
        kv[q] = make_float2(sc*kre[(size_t)q*PLSZ + px], sc*kim[(size_t)q*PLSZ + px]);
    #pragma unroll 1
    for (int c = 0; c < 16; ++c){
        float2 vin[5];
        #pragma unroll
        for (int a = 0; a < 5; ++a)
            vin[a] = h2f(*reinterpret_cast<const unsigned*>(
                &g_bufB[((size_t)(a*16 + c))*PLSZ + px]));
        #pragma unroll
        for (int b = 0; b < 5; ++b){
            float2 acc = make_float2(0.f, 0.f);
            #pragma unroll
            for (int a = 0; a < 5; ++a){
                float2 k2 = kv[b*5 + a];
                acc.x += k2.x*vin[a].x - k2.y*vin[a].y;
                acc.y += k2.x*vin[a].y + k2.y*vin[a].x;
            }
            *reinterpret_cast<unsigned*>(&g_bufA[((size_t)(b*16 + c))*PLSZ + px])
                = f2hu(acc.x, acc.y);
        }
    }
}

// ---------------- K4: column inverse (384 thr, all active) ----------------
__global__ void __launch_bounds__(384, 3) k_col_inv(){
    extern __shared__ unsigned s[];              // 6144
    int p = blockIdx.y, x0 = blockIdx.x*8, tid = threadIdx.x;
    int col = tid & 7, idx = tid >> 3;
    {
        float2 a[16];
        #pragma unroll
        for (int r = 0; r < 16; ++r)
            a[r] = h2f(*reinterpret_cast<const unsigned*>(
                &g_bufA[((size_t)p*OSN + idx + 48*r)*OSN + x0 + col]));
        dft16_pass1<true>(a);
        fft_stAB<3,true>(a, s, idx, col);
    }
    size_t pb = (size_t)p*OSN*OSN + x0;
    #pragma unroll 1
    for (int w = tid; w < 2048; w += 384){
        int kk = w >> 3, c = w & 7;
        int b3 = stC_base<3>(kk, c);
        float2 a0 = h2f(s[b3       ]);
        float2 a1 = h2f(s[b3 + 2048]);
        float2 a2 = h2f(s[b3 + 4096]);
        rad3t<true>(a0, a1, a2, g_twidC[kk]);
        if (kk >= PAD)
            *reinterpret_cast<unsigned*>(&g_bufB[pb + c + (size_t)(kk      )*OSN]) = f2hu2(a0);
        *reinterpret_cast<unsigned*>(&g_bufB[pb + c + (size_t)(kk + 256)*OSN]) = f2hu2(a1);
        if (kk < 64)
            *reinterpret_cast<unsigned*>(&g_bufB[pb + c + (size_t)(kk + 512)*OSN]) = f2hu2(a2);
    }
}

// ---------------- K5: row inverse (192 thr, all active) ----------------
__global__ void __launch_bounds__(192, 6) k_row_inv(float* __restrict__ out){
    extern __shared__ unsigned s[];              // 3072
    int p = blockIdx.y, oy0 = blockIdx.x*4, tid = threadIdx.x;
    int col = tid & 3, idx = tid >> 2;
    {
        size_t rb = ((size_t)p*OSN + PAD + oy0 + col)*OSN;
        float2 a[16];
        #pragma unroll
        for (int r = 0; r < 16; ++r)
            a[r] = h2f(*reinterpret_cast<const unsigned*>(&g_bufB[rb + idx + 48*r]));
        dft16_pass1<true>(a);
        fft_stAB<2,true>(a, s, idx, col);
    }
    #pragma unroll 1
    for (int w = tid; w < 1024; w += 192){
        int kk = w >> 2, c = w & 3;
        int b3 = stC_base<2>(kk, c);
        float2 a0 = h2f(s[b3       ]);
        float2 a1 = h2f(s[b3 + 1024]);
        float2 a2 = h2f(s[b3 + 2048]);
        rad3t<true>(a0, a1, a2, g_twidC[kk]);
        int oy = oy0 + c;
        float sg = ((oy + kk) & 1) ? -1.f : 1.f;
        size_t ob = ((size_t)p*NYI + oy)*NYI;
        if (kk >= PAD){
            int ox = kk - PAD;
            out[ob + ox]            = sg*a0.x;
            out[ob + ox + HALF_OUT] = sg*a0.y;
        }
        {
            int ox = kk + 256 - PAD;
            out[ob + ox]            = sg*a1.x;
            out[ob + ox + HALF_OUT] = sg*a1.y;
        }
        if (kk < 64){
            int ox = kk + 512 - PAD;
            out[ob + ox]            = sg*a2.x;
            out[ob + ox + HALF_OUT] = sg*a2.y;
        }
    }
}

extern "C" void kernel_launch(void* const* d_in, const int* in_sizes, int n_in,
                              void* d_out, int out_size){
    const float* ire = (const float*)d_in[0];
    const float* iim = (const float*)d_in[1];
    const float* kre = (const float*)d_in[2];
    const float* kim = (const float*)d_in[3];
    float* out = (float*)d_out;

    const int SM_ROW = 3072*sizeof(unsigned);   // 12288
    const int SM_COL = 6144*sizeof(unsigned);   // 24576
    cudaFuncSetAttribute(k_row_fwd, cudaFuncAttributeMaxDynamicSharedMemorySize, SM_ROW);
    cudaFuncSetAttribute(k_row_inv, cudaFuncAttributeMaxDynamicSharedMemorySize, SM_ROW);
    cudaFuncSetAttribute(k_col_fwd, cudaFuncAttributeMaxDynamicSharedMemorySize, SM_COL);
    cudaFuncSetAttribute(k_col_inv, cudaFuncAttributeMaxDynamicSharedMemorySize, SM_COL);

    k_twid<<<1, 256>>>();
    k_noop<<<1, 32>>>();                       // capture slot -> k_col_fwd

    k_row_fwd<<<dim3(96, NPL), 192, SM_ROW>>>(ire, iim);
    k_col_fwd<<<dim3(96, NPL), 384, SM_COL>>>();
    k_einsum<<<(PLSZ + 255)/256, 256>>>(kre, kim);
    k_col_inv<<<dim3(96, NPL), 384, SM_COL>>>();
    k_row_inv<<<dim3(96, NPL), 192, SM_ROW>>>(out);
}

// round 12
// speedup vs baseline: 1.0378x; 1.0378x over previous
#include <cuda_runtime.h>
#include <cuda_fp16.h>
#include <math.h>

#define NPL   80
#define NYI   384
#define OSN   768
#define PAD   192
#define PLSZ  (768*768)
#define HALF_OUT ((size_t)NPL*NYI*NYI)

__device__ __half2 g_bufA[(size_t)NPL*OSN*OSN];
__device__ __half2 g_bufB[(size_t)NPL*OSN*OSN];
__device__ float4  g_twidB[128];   // [k][j]: {w^{3(2j)k}, w^{3(2j+1)k}}, w = e^{-2pi i/768}
__device__ float4  g_twidC[256];   // [k]:    {w^{k}, w^{2k}}

__constant__ float2 c_w16[10] = {
    { 1.0f,            0.0f},
    { 0.9238795325f,  -0.3826834324f},
    { 0.7071067812f,  -0.7071067812f},
    { 0.3826834324f,  -0.9238795325f},
    { 0.0f,           -1.0f},
    {-0.3826834324f,  -0.9238795325f},
    {-0.7071067812f,  -0.7071067812f},
    {-0.9238795325f,  -0.3826834324f},
    {-1.0f,            0.0f},
    {-0.9238795325f,   0.3826834324f}
};

__device__ __forceinline__ float2 cmulf(float2 a, float2 b){
    return make_float2(a.x*b.x - a.y*b.y, a.x*b.y + a.y*b.x);
}
__device__ __forceinline__ float2 caddf(float2 a, float2 b){ return make_float2(a.x+b.x, a.y+b.y); }
__device__ __forceinline__ float2 csubf(float2 a, float2 b){ return make_float2(a.x-b.x, a.y-b.y); }

template<bool INV>
__device__ __forceinline__ float2 twmul(float2 a, float2 w){
    if (INV) w.y = -w.y;
    return cmulf(a, w);
}

__device__ __forceinline__ unsigned f2hu(float x, float y){
    __half2 h = __floats2half2_rn(x, y);
    return *reinterpret_cast<unsigned*>(&h);
}
__device__ __forceinline__ float2 h2f(unsigned u){
    __half2 h = *reinterpret_cast<__half2*>(&u);
    return __half22float2(h);
}
__device__ __forceinline__ unsigned f2hu2(float2 v){ return f2hu(v.x, v.y); }

__global__ void k_twid(){
    int t = blockIdx.x*blockDim.x + threadIdx.x;
    const double TPI = -2.0*3.14159265358979323846/768.0;
    if (t < 128){
        int k = t >> 3, j = t & 7;
        double a0 = TPI*(double)(3*(2*j  )*k);
        double a1 = TPI*(double)(3*(2*j+1)*k);
        g_twidB[t] = make_float4((float)cos(a0), (float)sin(a0),
                                 (float)cos(a1), (float)sin(a1));
    }
    if (t < 256){
        double a0 = TPI*(double)t;
        double a1 = TPI*(double)(2*t);
        g_twidC[t] = make_float4((float)cos(a0), (float)sin(a0),
                                 (float)cos(a1), (float)sin(a1));
    }
}

template<bool INV>
__device__ __forceinline__ void dft4(float2 &a0, float2 &a1, float2 &a2, float2 &a3){
    float2 t0=caddf(a0,a2), t1=csubf(a0,a2), t2=caddf(a1,a3), t3=csubf(a1,a3);
    a0 = caddf(t0,t2);  a2 = csubf(t0,t2);
    if (!INV){ a1 = make_float2(t1.x + t3.y, t1.y - t3.x);
               a3 = make_float2(t1.x - t3.y, t1.y + t3.x); }
    else     { a1 = make_float2(t1.x - t3.y, t1.y + t3.x);
               a3 = make_float2(t1.x + t3.y, t1.y - t3.x); }
}
template<bool INV>
__device__ __forceinline__ void dft16_pass1(float2 a[16]){
    #pragma unroll
    for (int n2 = 0; n2 < 4; ++n2)
        dft4<INV>(a[n2], a[n2+4], a[n2+8], a[n2+12]);
}
// pass1 specialized for inputs only in a[4..11] (legs 0,3 are exact zeros)
template<bool INV>
__device__ __forceinline__ void dft16_pass1_pruned(float2 a[16]){
    #pragma unroll
    for (int n2 = 0; n2 < 4; ++n2){
        float2 X = a[n2+4], Y = a[n2+8];     // dft4(0, X, Y, 0)
        float2 o0 = caddf(Y, X);
        float2 o2 = csubf(Y, X);
        float2 o1, o3;
        if (!INV){
            o1 = make_float2(X.y - Y.x, -(X.x + Y.y));
            o3 = make_float2(-(X.y + Y.x), X.x - Y.y);
        } else {
            o1 = make_float2(-(Y.x + X.y), X.x - Y.y);
            o3 = make_float2(X.y - Y.x, -(X.x + Y.y));
        }
        a[n2]=o0; a[n2+4]=o1; a[n2+8]=o2; a[n2+12]=o3;
    }
}
template<bool INV>
__device__ __forceinline__ void dft16_pass2(const float2 a[16], int k1, float2 y[4]){
    y[0] = a[4*k1];
    y[1] = twmul<INV>(a[4*k1+1], c_w16[k1]);
    y[2] = twmul<INV>(a[4*k1+2], c_w16[2*k1]);
    y[3] = twmul<INV>(a[4*k1+3], c_w16[3*k1]);
    dft4<INV>(y[0], y[1], y[2], y[3]);
}
template<bool INV>
__device__ __forceinline__ void rad3t(float2 &a0, float2 &a1, float2 &a2, float4 wc){
    a1 = twmul<INV>(a1, make_float2(wc.x, wc.y));
    a2 = twmul<INV>(a2, make_float2(wc.z, wc.w));
    float2 t = caddf(a1, a2);
    float2 d = csubf(a1, a2);
    float2 b0 = caddf(a0, t);
    float2 u  = make_float2(a0.x - 0.5f*t.x, a0.y - 0.5f*t.y);
    const float S = INV ? 0.86602540378443864676f : -0.86602540378443864676f;
    a0 = b0;
    a1 = make_float2(u.x - S*d.y, u.y + S*d.x);
    a2 = make_float2(u.x + S*d.y, u.y - S*d.x);
}

// Stage A store + stage B (strength-reduced swizzled smem addressing).
template<int LGN, bool INV>
__device__ __forceinline__ void fft_stAB(float2 a[16], unsigned* s, int idx, int col){
    const int NB = 1 << LGN;
    const int KW = (LGN == 2) ? 7 : 15;
    const int KS = LGN;
    {
        const int baseA = idx*(16*NB) + col;
        const int keyA  = (idx & KW) << KS;
        #pragma unroll
        for (int k1 = 0; k1 < 4; ++k1){
            float2 y[4];
            dft16_pass2<INV>(a, k1, y);
            #pragma unroll
            for (int k2 = 0; k2 < 4; ++k2){
                const int off = (k1 + 4*k2)*NB;
                s[baseA + (off ^ keyA)] = f2hu2(y[k2]);
            }
        }
    }
    __syncthreads();
    {
        const int b0 = idx*NB + col;
        const int q  = idx >> 4;
        #pragma unroll
        for (int r = 0; r < 16; ++r){
            const int key = ((q + 3*r) & KW) << KS;
            a[r] = h2f(s[(b0 ^ key) + 48*NB*r]);
        }
        const int k = idx & 15;
        #pragma unroll
        for (int j = 0; j < 8; ++j){
            float4 w2 = g_twidB[k*8 + j];
            if (j > 0) a[2*j] = twmul<INV>(a[2*j], make_float2(w2.x, w2.y));
            a[2*j+1] = twmul<INV>(a[2*j+1], make_float2(w2.z, w2.w));
        }
        dft16_pass1<INV>(a);
    }
    __syncthreads();
    {
        const int k  = idx & 15, j = idx >> 4;
        const int t  = k*NB + col;
        const int Cj = j*(256*NB);
        #pragma unroll
        for (int k1 = 0; k1 < 4; ++k1){
            float2 y[4];
            dft16_pass2<INV>(a, k1, y);
            #pragma unroll
            for (int k2 = 0; k2 < 4; ++k2){
                const int off = k1 + 4*k2;
                s[Cj + off*(16*NB) + (t ^ ((off & KW) << KS))] = f2hu2(y[k2]);
            }
        }
    }
    __syncthreads();
}

template<int LGN>
__device__ __forceinline__ int stC_base(int kk, int col){
    const int KW = (LGN == 2) ? 7 : 15;
    return (kk*(1<<LGN) + col) ^ (((kk >> 4) & KW) << LGN);
}

// ---------------- K1: row forward ----------------
__global__ void __launch_bounds__(256) k_row_fwd(const float* __restrict__ re,
                                                 const float* __restrict__ im){
    extern __shared__ unsigned s[];              // 3072
    int p = blockIdx.y, iy0 = blockIdx.x*4, tid = threadIdx.x;
    int col = tid & 3, idx = tid >> 2;
    if (tid < 192){
        int iy = iy0 + col;
        size_t rb = ((size_t)p*NYI + iy)*NYI;
        float2 a[16];
        #pragma unroll
        for (int q = 0; q < 8; ++q){
            int ix = idx + 48*q;
            float sg = ((iy + ix) & 1) ? -1.f : 1.f;
            a[q+4] = make_float2(sg*re[rb + ix], sg*im[rb + ix]);
        }
        dft16_pass1_pruned<false>(a);
        fft_stAB<2,false>(a, s, idx, col);
    } else {
        __syncthreads(); __syncthreads(); __syncthreads();
    }
    int c = tid & 3, kk0 = tid >> 2;
    size_t base = ((size_t)p*OSN + PAD + iy0 + c)*OSN;
    #pragma unroll
    for (int i = 0; i < 4; ++i){
        int kk = kk0 + 64*i;
        int b3 = stC_base<2>(kk, c);
        float2 a0 = h2f(s[b3       ]);
        float2 a1 = h2f(s[b3 + 1024]);
        float2 a2 = h2f(s[b3 + 2048]);
        rad3t<false>(a0, a1, a2, g_twidC[kk]);
        *reinterpret_cast<unsigned*>(&g_bufA[base + kk      ]) = f2hu2(a0);
        *reinterpret_cast<unsigned*>(&g_bufA[base + kk + 256]) = f2hu2(a1);
        *reinterpret_cast<unsigned*>(&g_bufA[base + kk + 512]) = f2hu2(a2);
    }
}

// ---------------- K2: column forward ----------------
__global__ void __launch_bounds__(512) k_col_fwd(){
    extern __shared__ unsigned s[];              // 6144
    int p = blockIdx.y, x0 = blockIdx.x*8, tid = threadIdx.x;
    int col = tid & 7, idx = tid >> 3;
    if (tid < 384){
        float2 a[16];
        #pragma unroll
        for (int q = 0; q < 8; ++q){
            int y = idx + 48*q + PAD;
            a[q+4] = h2f(*reinterpret_cast<const unsigned*>(
                &g_bufA[((size_t)p*OSN + y)*OSN + x0 + col]));
        }
        dft16_pass1_pruned<false>(a);
        fft_stAB<3,false>(a, s, idx, col);
    } else {
        __syncthreads(); __syncthreads(); __syncthreads();
    }
    int c = tid & 7, kk0 = tid >> 3;
    size_t pb = (size_t)p*OSN*OSN + x0 + c;
    #pragma unroll
    for (int i = 0; i < 4; ++i){
        int kk = kk0 + 64*i;
        int b3 = stC_base<3>(kk, c);
        float2 a0 = h2f(s[b3       ]);
        float2 a1 = h2f(s[b3 + 2048]);
        float2 a2 = h2f(s[b3 + 4096]);
        rad3t<false>(a0, a1, a2, g_twidC[kk]);
        *reinterpret_cast<unsigned*>(&g_bufB[pb + (size_t)(kk      )*OSN]) = f2hu2(a0);
        *reinterpret_cast<unsigned*>(&g_bufB[pb + (size_t)(kk + 256)*OSN]) = f2hu2(a1);
        *reinterpret_cast<unsigned*>(&g_bufB[pb + (size_t)(kk + 512)*OSN]) = f2hu2(a2);
    }
}

// ---------------- K3: einsum, software-pipelined coil loop ----------------
__global__ void __launch_bounds__(256, 3) k_einsum(const float* __restrict__ kre,
                                                   const float* __restrict__ kim){
    int px = blockIdx.x*256 + threadIdx.x;
    if (px >= PLSZ) return;
    const float sc = 1.0f/589824.0f;
    float2 kv[25];
    #pragma unroll
    for (int q = 0; q < 25; ++q)
        kv[q] = make_float2(sc*kre[(size_t)q*PLSZ + px], sc*kim[(size_t)q*PLSZ + px]);
    // prefetch coil 0
    unsigned vnx[5];
    #pragma unroll
    for (int a = 0; a < 5; ++a)
        vnx[a] = *reinterpret_cast<const unsigned*>(&g_bufB[((size_t)(a*16))*PLSZ + px]);
    #pragma unroll 1
    for (int c = 0; c < 16; ++c){
        float2 vin[5];
        #pragma unroll
        for (int a = 0; a < 5; ++a) vin[a] = h2f(vnx[a]);
        if (c < 15){
            #pragma unroll
            for (int a = 0; a < 5; ++a)
                vnx[a] = *reinterpret_cast<const unsigned*>(
                    &g_bufB[((size_t)(a*16 + c + 1))*PLSZ + px]);
        }
        #pragma unroll
        for (int b = 0; b < 5; ++b){
            float2 acc = make_float2(0.f, 0.f);
            #pragma unroll
            for (int a = 0; a < 5; ++a){
                float2 k2 = kv[b*5 + a];
                acc.x += k2.x*vin[a].x - k2.y*vin[a].y;
                acc.y += k2.x*vin[a].y + k2.y*vin[a].x;
            }
            *reinterpret_cast<unsigned*>(&g_bufA[((size_t)(b*16 + c))*PLSZ + px])
                = f2hu(acc.x, acc.y);
        }
    }
}

// ---------------- K4: column inverse ----------------
__global__ void __launch_bounds__(512) k_col_inv(){
    extern __shared__ unsigned s[];              // 6144
    int p = blockIdx.y, x0 = blockIdx.x*8, tid = threadIdx.x;
    int col = tid & 7, idx = tid >> 3;
    if (tid < 384){
        float2 a[16];
        #pragma unroll
        for (int r = 0; r < 16; ++r)
            a[r] = h2f(*reinterpret_cast<const unsigned*>(
                &g_bufA[((size_t)p*OSN + idx + 48*r)*OSN + x0 + col]));
        dft16_pass1<true>(a);
        fft_stAB<3,true>(a, s, idx, col);
    } else {
        __syncthreads(); __syncthreads(); __syncthreads();
    }
    int c = tid & 7, kk0 = tid >> 3;
    size_t pb = (size_t)p*OSN*OSN + x0 + c;
    #pragma unroll
    for (int i = 0; i < 4; ++i){
        int kk = kk0 + 64*i;
        int b3 = stC_base<3>(kk, c);
        float2 a0 = h2f(s[b3       ]);
        float2 a1 = h2f(s[b3 + 2048]);
        float2 a2 = h2f(s[b3 + 4096]);
        rad3t<true>(a0, a1, a2, g_twidC[kk]);
        if (kk >= PAD)
            *reinterpret_cast<unsigned*>(&g_bufB[pb + (size_t)(kk      )*OSN]) = f2hu2(a0);
        *reinterpret_cast<unsigned*>(&g_bufB[pb + (size_t)(kk + 256)*OSN]) = f2hu2(a1);
        if (kk < 64)
            *reinterpret_cast<unsigned*>(&g_bufB[pb + (size_t)(kk + 512)*OSN]) = f2hu2(a2);
    }
}

// ---------------- K5: row inverse ----------------
__global__ void __launch_bounds__(256) k_row_inv(float* __restrict__ out){
    extern __shared__ unsigned s[];              // 3072
    int p = blockIdx.y, oy0 = blockIdx.x*4, tid = threadIdx.x;
    int col = tid & 3, idx = tid >> 2;
    if (tid < 192){
        size_t rb = ((size_t)p*OSN + PAD + oy0 + col)*OSN;
        float2 a[16];
        #pragma unroll
        for (int r = 0; r < 16; ++r)
            a[r] = h2f(*reinterpret_cast<const unsigned*>(&g_bufB[rb + idx + 48*r]));
        dft16_pass1<true>(a);
        fft_stAB<2,true>(a, s, idx, col);
    } else {
        __syncthreads(); __syncthreads(); __syncthreads();
    }
    int c = tid & 3, kk0 = tid >> 2;
    int oy = oy0 + c;
    size_t ob = ((size_t)p*NYI + oy)*NYI;
    #pragma unroll
    for (int i = 0; i < 4; ++i){
        int kk = kk0 + 64*i;
        int b3 = stC_base<2>(kk, c);
        float2 a0 = h2f(s[b3       ]);
        float2 a1 = h2f(s[b3 + 1024]);
        float2 a2 = h2f(s[b3 + 2048]);
        rad3t<true>(a0, a1, a2, g_twidC[kk]);
        float sg = ((oy + kk) & 1) ? -1.f : 1.f;
        if (kk >= PAD){
            int ox = kk - PAD;
            out[ob + ox]            = sg*a0.x;
            out[ob + ox + HALF_OUT] = sg*a0.y;
        }
        {
            int ox = kk + 256 - PAD;
            out[ob + ox]            = sg*a1.x;
            out[ob + ox + HALF_OUT] = sg*a1.y;
        }
        if (kk < 64){
            int ox = kk + 512 - PAD;
            out[ob + ox]            = sg*a2.x;
            out[ob + ox + HALF_OUT] = sg*a2.y;
        }
    }
}

extern "C" void kernel_launch(void* const* d_in, const int* in_sizes, int n_in,
                              void* d_out, int out_size){
    const float* ire = (const float*)d_in[0];
    const float* iim = (const float*)d_in[1];
    const float* kre = (const float*)d_in[2];
    const float* kim = (const float*)d_in[3];
    float* out = (float*)d_out;

    const int SM_ROW = 3072*sizeof(unsigned);   // 12288
    const int SM_COL = 6144*sizeof(unsigned);   // 24576
    cudaFuncSetAttribute(k_row_fwd, cudaFuncAttributeMaxDynamicSharedMemorySize, SM_ROW);
    cudaFuncSetAttribute(k_row_inv, cudaFuncAttributeMaxDynamicSharedMemorySize, SM_ROW);
    cudaFuncSetAttribute(k_col_fwd, cudaFuncAttributeMaxDynamicSharedMemorySize, SM_COL);
    cudaFuncSetAttribute(k_col_inv, cudaFuncAttributeMaxDynamicSharedMemorySize, SM_COL);

    k_twid<<<1, 256>>>();

    k_row_fwd<<<dim3(96, NPL), 256, SM_ROW>>>(ire, iim);
    k_col_fwd<<<dim3(96, NPL), 512, SM_COL>>>();
    k_einsum<<<(PLSZ + 255)/256, 256>>>(kre, kim);   // launch #4 -> ncu capture slot
    k_col_inv<<<dim3(96, NPL), 512, SM_COL>>>();
    k_row_inv<<<dim3(96, NPL), 256, SM_ROW>>>(out);
}